// round 13
// baseline (speedup 1.0000x reference)
#include <cuda_runtime.h>
#include <cuda_fp16.h>
#include <mma.h>

using namespace nvcuda;

#define Bsz  4096
#define Nseq 512
#define Csz  512
#define PHId 128
#define H1d  512
#define H2d  256

// Scratch (__device__ globals; no allocations allowed)
__device__ __half g_hist [Bsz * Csz];    // 4 MB   per-row label histogram (fp16, exact)
__device__ __half g_h1   [Bsz * H1d];    // 4 MB
__device__ float  g_part [4 * Bsz];      // partial dots (deterministic reduce)
__device__ __half g_Wc   [Csz * H1d];    // 512 KB  Wc = Wphi @ W1 (fp16)
__device__ __half g_W2   [H1d * H2d];
__device__ float  g_b1eff[H1d];          // b1 + 512 * (b_phi @ W1), exact fp32
__device__ int    g_flags[128];          // dependency counters (memset per call)
// flag map: [0,64) hist row-groups (target 8); [64,72) Wc col-groups (target 8); [72] b1eff

// kernel-A block ranges (bid order == dependency order)
#define NH    512     // hist: 8 rows/block
#define WC0   512     // 64 Wc blocks
#define W20   576     // 32 W2-convert blocks
#define B10   608     // 1 b1eff block
#define G10   609     // 512 gemm1 blocks
#define NBLKA 1121

// ---------------------------------------------------------------------------
__device__ __forceinline__ void cp_async16(void* smem, const void* gmem) {
    unsigned s = (unsigned)__cvta_generic_to_shared(smem);
    asm volatile("cp.async.cg.shared.global [%0], [%1], 16;\n" :: "r"(s), "l"(gmem));
}
__device__ __forceinline__ void cp_commit() {
    asm volatile("cp.async.commit_group;\n");
}
template <int NN>
__device__ __forceinline__ void cp_wait() {
    asm volatile("cp.async.wait_group %0;\n" :: "n"(NN));
}
__device__ __forceinline__ void spinwait(volatile int* p, int tgt) {
    while (*p < tgt) __nanosleep(32);
}
__device__ __forceinline__ void release(int* flag) {
    __threadfence();
    __syncthreads();
    if (threadIdx.x == 0) atomicAdd(flag, 1);
}

// ---------------------------------------------------------------------------
// Shared GEMM body: BM=BN=BK=64, 128 threads, 4 warps (2x2), warp tile 32x32,
// 2-stage cp.async pipeline, one barrier per k-iter. fp16 in, fp32 acc.
// (verified correct in R9/R11 runs)
// ---------------------------------------------------------------------------
template <bool FUSED>
__device__ __forceinline__ void gemm_body(char* smraw,
                                          const __half* __restrict__ A,
                                          const __half* __restrict__ B,
                                          const float* __restrict__ bias,
                                          const float* __restrict__ w3,
                                          __half* __restrict__ C,
                                          float* __restrict__ partRow,
                                          int rowBase, int colBase, int N, int K)
{
    __half* sh = reinterpret_cast<__half*>(smraw);
    const int tid = threadIdx.x, warp = tid >> 5;
    const int wr = warp & 1, wc = warp >> 1;
    const int lr = tid >> 3, lc = (tid & 7) << 3;

    auto SA = [&](int s, int r) { return sh + (s * 64 + r) * 72; };
    auto SB = [&](int s, int r) { return sh + 9216 + (s * 64 + r) * 72; };

    auto load_tile = [&](int s, int kt) {
        const __half* Ak = A + (size_t)rowBase * K + kt * 64;
#pragma unroll
        for (int r = 0; r < 4; r++)
            cp_async16(SA(s, lr + 16 * r) + lc, Ak + (size_t)(lr + 16 * r) * K + lc);
        const __half* Bk = B + (size_t)(kt * 64) * N + colBase;
#pragma unroll
        for (int r = 0; r < 4; r++)
            cp_async16(SB(s, lr + 16 * r) + lc, Bk + (size_t)(lr + 16 * r) * N + lc);
    };

    wmma::fragment<wmma::accumulator, 16, 16, 16, float> acc[2][2];
#pragma unroll
    for (int i = 0; i < 2; i++)
#pragma unroll
        for (int j = 0; j < 2; j++) wmma::fill_fragment(acc[i][j], 0.f);

    const int KT = K / 64;
    load_tile(0, 0); cp_commit();

    for (int kt = 0; kt < KT; kt++) {
        cp_wait<0>();
        __syncthreads();
        if (kt + 1 < KT) load_tile((kt + 1) & 1, kt + 1);
        cp_commit();

        const int s = kt & 1;
#pragma unroll
        for (int kk = 0; kk < 4; kk++) {
            wmma::fragment<wmma::matrix_a, 16, 16, 16, __half, wmma::row_major> af[2];
            wmma::fragment<wmma::matrix_b, 16, 16, 16, __half, wmma::row_major> bf[2];
#pragma unroll
            for (int i = 0; i < 2; i++)
                wmma::load_matrix_sync(af[i], SA(s, wr * 32 + i * 16) + kk * 16, 72);
#pragma unroll
            for (int j = 0; j < 2; j++)
                wmma::load_matrix_sync(bf[j], SB(s, kk * 16) + wc * 32 + j * 16, 72);
#pragma unroll
            for (int i = 0; i < 2; i++)
#pragma unroll
                for (int j = 0; j < 2; j++)
                    wmma::mma_sync(acc[i][j], af[i], bf[j], acc[i][j]);
        }
    }
    __syncthreads();

    float* Cs = reinterpret_cast<float*>(smraw);       // [64][68]
#pragma unroll
    for (int i = 0; i < 2; i++)
#pragma unroll
        for (int j = 0; j < 2; j++)
            wmma::store_matrix_sync(&Cs[(wr * 32 + i * 16) * 68 + wc * 32 + j * 16],
                                    acc[i][j], 68, wmma::mem_row_major);
    __syncthreads();

    if (!FUSED) {
#pragma unroll
        for (int e = tid; e < 64 * 8; e += 128) {
            const int r = e >> 3, c = (e & 7) << 3;
            __half h8[8];
#pragma unroll
            for (int q = 0; q < 8; q++)
                h8[q] = __float2half(fmaxf(Cs[r * 68 + c + q] + bias[colBase + c + q], 0.f));
            *reinterpret_cast<int4*>(&C[(size_t)(rowBase + r) * N + colBase + c]) =
                *reinterpret_cast<int4*>(h8);
        }
    } else {
        float* sp = reinterpret_cast<float*>(smraw + 17408);   // after Cs, inside old B area
        const int r = tid >> 1, sc = (tid & 1) << 5;
        float v = 0.f;
#pragma unroll
        for (int i = 0; i < 32; i++) {
            const float h = fmaxf(Cs[r * 68 + sc + i] + bias[colBase + sc + i], 0.f);
            v = fmaf(h, w3[colBase + sc + i], v);
        }
        sp[r * 2 + (tid & 1)] = v;
        __syncthreads();
        if (tid < 64) partRow[tid] = sp[tid * 2] + sp[tid * 2 + 1];
    }
}

// ---------------------------------------------------------------------------
// Kernel A: prep (hist + Wc + W2 + b1eff) AND gemm1, overlapped.
// gemm1 blocks (bids >= G10) spin on hist/Wc/b1 flags; hist is ATOMS-bound so
// gemm1's tensor/cp.async work hides underneath it on shared SMs.
// All 609 prep blocks are wave-1 resident (6 blocks/SM x 148 = 888 slots);
// waiters depend only on strictly lower bids -> no deadlock.
// ---------------------------------------------------------------------------
__global__ void __launch_bounds__(128) fusedA_kernel(const int* __restrict__ x,
                                                     const float* __restrict__ Wphi,
                                                     const float* __restrict__ W1,
                                                     const float* __restrict__ W2,
                                                     const float* __restrict__ bphi,
                                                     const float* __restrict__ b1)
{
    __shared__ __align__(16) char praw[36864];
    const int tid = threadIdx.x;
    const int bid = blockIdx.x;
    volatile int* vf = g_flags;

    if (bid < NH) {
        // ---- histogram: 8 rows/block, 4 warps x 2 rows, smem atomics ----
        int* hs = reinterpret_cast<int*>(praw);        // [8][512]
#pragma unroll
        for (int i = 0; i < 8; i++)
            reinterpret_cast<int4*>(hs)[tid + i * 128] = make_int4(0, 0, 0, 0);
        __syncthreads();

        const int warp = tid >> 5, lane = tid & 31;
#pragma unroll
        for (int rr = 0; rr < 2; rr++) {
            const int r8 = warp * 2 + rr;
            const int4* xr = reinterpret_cast<const int4*>(
                x + ((size_t)bid * 8 + r8) * Nseq);
            int* hw = hs + r8 * Csz;
#pragma unroll
            for (int i = 0; i < 4; i++) {
                const int4 v = xr[lane + i * 32];
                atomicAdd(&hw[v.x], 1);
                atomicAdd(&hw[v.y], 1);
                atomicAdd(&hw[v.z], 1);
                atomicAdd(&hw[v.w], 1);
            }
        }
        __syncthreads();

        __half* dst = g_hist + (size_t)bid * 8 * Csz;
#pragma unroll
        for (int i = 0; i < 8; i++) {
            const int e4 = tid + i * 128;
            const int4 c = reinterpret_cast<const int4*>(hs)[e4];
            __half h4[4] = {__float2half((float)c.x), __float2half((float)c.y),
                            __float2half((float)c.z), __float2half((float)c.w)};
            *reinterpret_cast<uint2*>(&dst[e4 * 4]) = *reinterpret_cast<uint2*>(h4);
        }
        release(&g_flags[bid >> 3]);                   // row-group = 64 rows
    } else if (bid < W20) {
        // ---- Wc = Wphi @ W1 (HMMA), 64x64 tile, K=128 ----
        const int cb = bid - WC0;                      // 0..63 -> 8x8 tiles
        const int tr = (cb >> 3) * 64, tcc = (cb & 7) * 64;
        __half* sA = reinterpret_cast<__half*>(praw);           // ld 136
        __half* sB = reinterpret_cast<__half*>(praw + 17408);   // ld 72
        float*  sC = reinterpret_cast<float*>(praw);            // ld 68 (aliases sA)

#pragma unroll
        for (int i = 0; i < 16; i++) {
            const int idx = i * 128 + tid;             // 2048 float4 of A
            const int r = idx >> 5, c4 = (idx & 31) << 2;
            const float4 v = *reinterpret_cast<const float4*>(
                &Wphi[(size_t)(tr + r) * PHId + c4]);
            __half h4[4] = {__float2half(v.x), __float2half(v.y),
                            __float2half(v.z), __float2half(v.w)};
            *reinterpret_cast<uint2*>(&sA[r * 136 + c4]) = *reinterpret_cast<uint2*>(h4);
        }
#pragma unroll
        for (int i = 0; i < 16; i++) {
            const int idx = i * 128 + tid;             // 2048 float4 of B
            const int r = idx >> 4, c4 = (idx & 15) << 2;
            const float4 v = *reinterpret_cast<const float4*>(
                &W1[(size_t)r * H1d + tcc + c4]);
            __half h4[4] = {__float2half(v.x), __float2half(v.y),
                            __float2half(v.z), __float2half(v.w)};
            *reinterpret_cast<uint2*>(&sB[r * 72 + c4]) = *reinterpret_cast<uint2*>(h4);
        }
        __syncthreads();

        // 4 warps, each one 16-col group over all 64 rows
        const int wcg = tid >> 5;
        wmma::fragment<wmma::accumulator, 16, 16, 16, float> ac[4];
#pragma unroll
        for (int i = 0; i < 4; i++) wmma::fill_fragment(ac[i], 0.f);
#pragma unroll
        for (int k = 0; k < 8; k++) {
            wmma::fragment<wmma::matrix_b, 16, 16, 16, __half, wmma::row_major> bf;
            wmma::load_matrix_sync(bf, &sB[(k * 16) * 72 + wcg * 16], 72);
#pragma unroll
            for (int i = 0; i < 4; i++) {
                wmma::fragment<wmma::matrix_a, 16, 16, 16, __half, wmma::row_major> af;
                wmma::load_matrix_sync(af, &sA[(i * 16) * 136 + k * 16], 136);
                wmma::mma_sync(ac[i], af, bf, ac[i]);
            }
        }
        __syncthreads();       // done reading sA before aliasing as sC
#pragma unroll
        for (int i = 0; i < 4; i++)
            wmma::store_matrix_sync(&sC[(i * 16) * 68 + wcg * 16], ac[i], 68,
                                    wmma::mem_row_major);
        __syncthreads();
#pragma unroll
        for (int e = tid; e < 64 * 8; e += 128) {
            const int r = e >> 3, c = (e & 7) << 3;
            __half h8[8];
#pragma unroll
            for (int q = 0; q < 8; q++) h8[q] = __float2half(sC[r * 68 + c + q]);
            *reinterpret_cast<int4*>(&g_Wc[(size_t)(tr + r) * H1d + tcc + c]) =
                *reinterpret_cast<int4*>(h8);
        }
        release(&g_flags[64 + (cb & 7)]);
    } else if (bid < B10) {
        // ---- W2 fp32 -> fp16 (consumed next launch, no flag) ----
        const int t = (bid - W20) * 128 + tid;         // 4096 threads
#pragma unroll
        for (int i = 0; i < 8; i++) {
            const int e4 = t + i * 4096;               // 32768 float4
            const float4 v = reinterpret_cast<const float4*>(W2)[e4];
            __half h4[4] = {__float2half(v.x), __float2half(v.y),
                            __float2half(v.z), __float2half(v.w)};
            *reinterpret_cast<uint2*>(&g_W2[e4 * 4]) = *reinterpret_cast<uint2*>(h4);
        }
    } else if (bid < G10) {
        // ---- b1_eff = b1 + 512*(b_phi @ W1) ----
#pragma unroll
        for (int q = 0; q < 4; q++) {
            const int o = tid * 4 + q;
            float s = 0.f;
            for (int k = 0; k < PHId; k++) s = fmaf(bphi[k], W1[k * H1d + o], s);
            g_b1eff[o] = b1[o] + (float)Nseq * s;
        }
        release(&g_flags[72]);
    } else {
        // ---- gemm1: h1 = relu(hist @ Wc + b1eff), gated on flags ----
        const int t = bid - G10;
        const int rowb = t >> 3, colb = t & 7;
        if (tid == 0) {
            spinwait(&vf[rowb], 8);        // 8 hist blocks cover this 64-row group
            spinwait(&vf[64 + colb], 8);   // 8 Wc blocks cover this 64-col group
            spinwait(&vf[72], 1);
        }
        __syncthreads();
        __threadfence();
        gemm_body<false>(praw, g_hist, g_Wc, g_b1eff, nullptr,
                         g_h1, nullptr, rowb * 64, colb * 64, H1d, Csz);
    }
}

// ---------------------------------------------------------------------------
// Kernel B: fused h2 = relu(h1 @ W2 + b2); partials = h2 @ W3 -> g_part
// ---------------------------------------------------------------------------
__global__ void __launch_bounds__(128) gemm2_kernel(const float* __restrict__ b2,
                                                    const float* __restrict__ W3)
{
    __shared__ __align__(16) char praw[36864];
    const int colb = blockIdx.x, rowb = blockIdx.y;
    gemm_body<true>(praw, g_h1, g_W2, b2, W3, nullptr,
                    g_part + (size_t)colb * Bsz + rowb * 64,
                    rowb * 64, colb * 64, H2d, H1d);
}

// ---------------------------------------------------------------------------
// Deterministic final reduce: out[i] = sum of 4 partials + b3.
// ---------------------------------------------------------------------------
__global__ void __launch_bounds__(256) reduce_kernel(const float* __restrict__ b3,
                                                     float* __restrict__ out)
{
    const int i = blockIdx.x * 256 + threadIdx.x;
    out[i] = ((g_part[i] + g_part[Bsz + i]) + (g_part[2 * Bsz + i] + g_part[3 * Bsz + i]))
             + b3[0];
}

// ---------------------------------------------------------------------------
extern "C" void kernel_launch(void* const* d_in, const int* in_sizes, int n_in,
                              void* d_out, int out_size)
{
    const int*   x    = (const int*)  d_in[0];
    const float* Wphi = (const float*)d_in[1];
    const float* bphi = (const float*)d_in[2];
    const float* W1   = (const float*)d_in[3];
    const float* b1   = (const float*)d_in[4];
    const float* W2   = (const float*)d_in[5];
    const float* b2   = (const float*)d_in[6];
    const float* W3   = (const float*)d_in[7];
    const float* b3   = (const float*)d_in[8];
    float* out = (float*)d_out;

    void* flags_p;
    cudaGetSymbolAddress(&flags_p, g_flags);
    cudaMemsetAsync(flags_p, 0, 128 * sizeof(int), 0);

    // A: prep + gemm1 overlapped (flag-gated)
    fusedA_kernel<<<NBLKA, 128>>>(x, Wphi, W1, W2, bphi, b1);

    // B: fused gemm2 -> partials
    {
        dim3 grid(H2d / 64, Bsz / 64);
        gemm2_kernel<<<grid, 128>>>(b2, W3);
    }
    // C: deterministic reduce + b3
    reduce_kernel<<<Bsz / 256, 256>>>(b3, out);
}